// round 2
// baseline (speedup 1.0000x reference)
#include <cuda_runtime.h>
#include <cstdint>

#define NUM_LEVELS 16
#define LOG2_T 19
#define TABLE_SIZE (1u << LOG2_T)
#define TABLE_MASK (TABLE_SIZE - 1u)
#define P1 2654435761u
#define P2 805459861u

// One thread per (point, level). 8 independent float2 gathers per thread.
__global__ __launch_bounds__(256) void hashenc_kernel(
    const float* __restrict__ x,
    const float* __restrict__ tables,
    float* __restrict__ out,
    int N)
{
    int gid = blockIdx.x * blockDim.x + threadIdx.x;
    if (gid >= N * NUM_LEVELS) return;
    int p = gid >> 4;          // point index
    int l = gid & 15;          // level index

    // load point (16 consecutive threads share the same point -> L1 broadcast)
    float x0 = x[p * 3 + 0];
    float x1 = x[p * 3 + 1];
    float x2 = x[p * 3 + 2];

    // normalize: clip((x+1)/2, 0, 1-1e-6)
    const float hi = 1.0f - 1e-6f;
    x0 = fminf(fmaxf((x0 + 1.0f) * 0.5f, 0.0f), hi);
    x1 = fminf(fmaxf((x1 + 1.0f) * 0.5f, 0.0f), hi);
    x2 = fminf(fmaxf((x2 + 1.0f) * 0.5f, 0.0f), hi);

    float res = (float)(16 << l);
    float s0 = x0 * res, s1 = x1 * res, s2 = x2 * res;
    float f0 = floorf(s0), f1 = floorf(s1), f2 = floorf(s2);
    float fx = s0 - f0, fy = s1 - f1, fz = s2 - f2;
    uint32_t ix = (uint32_t)(int)f0;
    uint32_t iy = (uint32_t)(int)f1;
    uint32_t iz = (uint32_t)(int)f2;

    // hash terms for the two coords per axis
    uint32_t ax0 = ix,            ax1 = ix + 1u;
    uint32_t ay0 = iy * P1,       ay1 = (iy + 1u) * P1;
    uint32_t az0 = iz * P2,       az1 = (iz + 1u) * P2;
    uint32_t lv = (uint32_t)l;

    const float2* __restrict__ tbl =
        (const float2*)tables + (size_t)l * TABLE_SIZE;

    // corner order matches OFFSETS: bit2=x, bit1=y, bit0=z
    uint32_t idx[8];
    idx[0] = (ax0 ^ ay0 ^ az0 ^ lv) & TABLE_MASK;
    idx[1] = (ax0 ^ ay0 ^ az1 ^ lv) & TABLE_MASK;
    idx[2] = (ax0 ^ ay1 ^ az0 ^ lv) & TABLE_MASK;
    idx[3] = (ax0 ^ ay1 ^ az1 ^ lv) & TABLE_MASK;
    idx[4] = (ax1 ^ ay0 ^ az0 ^ lv) & TABLE_MASK;
    idx[5] = (ax1 ^ ay0 ^ az1 ^ lv) & TABLE_MASK;
    idx[6] = (ax1 ^ ay1 ^ az0 ^ lv) & TABLE_MASK;
    idx[7] = (ax1 ^ ay1 ^ az1 ^ lv) & TABLE_MASK;

    // issue all 8 gathers up front (MLP)
    float2 e0 = __ldg(&tbl[idx[0]]);
    float2 e1 = __ldg(&tbl[idx[1]]);
    float2 e2 = __ldg(&tbl[idx[2]]);
    float2 e3 = __ldg(&tbl[idx[3]]);
    float2 e4 = __ldg(&tbl[idx[4]]);
    float2 e5 = __ldg(&tbl[idx[5]]);
    float2 e6 = __ldg(&tbl[idx[6]]);
    float2 e7 = __ldg(&tbl[idx[7]]);

    float gx = 1.0f - fx, gy = 1.0f - fy, gz = 1.0f - fz;
    float w0 = gx * gy * gz;
    float w1 = gx * gy * fz;
    float w2 = gx * fy * gz;
    float w3 = gx * fy * fz;
    float w4 = fx * gy * gz;
    float w5 = fx * gy * fz;
    float w6 = fx * fy * gz;
    float w7 = fx * fy * fz;

    float o0 = e0.x * w0 + e1.x * w1 + e2.x * w2 + e3.x * w3
             + e4.x * w4 + e5.x * w5 + e6.x * w6 + e7.x * w7;
    float o1 = e0.y * w0 + e1.y * w1 + e2.y * w2 + e3.y * w3
             + e4.y * w4 + e5.y * w5 + e6.y * w6 + e7.y * w7;

    // out[p, l*2 + {0,1}] ; row length = 32 floats.
    // Consecutive threads (same point, consecutive levels) -> contiguous 8B stores.
    float2* orow = (float2*)(out + (size_t)p * (NUM_LEVELS * 2));
    orow[l] = make_float2(o0, o1);
}

extern "C" void kernel_launch(void* const* d_in, const int* in_sizes, int n_in,
                              void* d_out, int out_size) {
    const float* x      = (const float*)d_in[0];
    const float* tables = (const float*)d_in[1];
    float* out          = (float*)d_out;
    int N = in_sizes[0] / 3;

    int total = N * NUM_LEVELS;
    int threads = 256;
    int blocks = (total + threads - 1) / threads;
    hashenc_kernel<<<blocks, threads>>>(x, tables, out, N);
}

// round 3
// speedup vs baseline: 1.0753x; 1.0753x over previous
#include <cuda_runtime.h>
#include <cstdint>

#define NUM_LEVELS 16
#define LOG2_T 19
#define TABLE_SIZE (1u << LOG2_T)
#define TABLE_MASK (TABLE_SIZE - 1u)
#define P1 2654435761u
#define P2 805459861u

// One thread per (point, level).
// Key trick: x-axis hash prime is 1, so for even ix the corner pair
// (ix, ix+1) maps to table indices {2m, 2m+1} -> one aligned float4 load
// fetches BOTH corner entries. 8 gathers -> 4 LDG.128 (even ix case).
__global__ __launch_bounds__(256) void hashenc_kernel(
    const float* __restrict__ x,
    const float* __restrict__ tables,
    float* __restrict__ out,
    int N)
{
    int gid = blockIdx.x * blockDim.x + threadIdx.x;
    if (gid >= N * NUM_LEVELS) return;
    int p = gid >> 4;          // point index
    int l = gid & 15;          // level index

    float x0 = x[p * 3 + 0];
    float x1 = x[p * 3 + 1];
    float x2 = x[p * 3 + 2];

    const float hi = 1.0f - 1e-6f;
    x0 = fminf(fmaxf((x0 + 1.0f) * 0.5f, 0.0f), hi);
    x1 = fminf(fmaxf((x1 + 1.0f) * 0.5f, 0.0f), hi);
    x2 = fminf(fmaxf((x2 + 1.0f) * 0.5f, 0.0f), hi);

    float res = (float)(16 << l);
    float s0 = x0 * res, s1 = x1 * res, s2 = x2 * res;
    float f0 = floorf(s0), f1 = floorf(s1), f2 = floorf(s2);
    float fx = s0 - f0, fy = s1 - f1, fz = s2 - f2;
    uint32_t ix = (uint32_t)(int)f0;
    uint32_t iy = (uint32_t)(int)f1;
    uint32_t iz = (uint32_t)(int)f2;

    uint32_t ay0 = iy * P1, ay1 = (iy + 1u) * P1;
    uint32_t az0 = iz * P2, az1 = (iz + 1u) * P2;
    uint32_t lv = (uint32_t)l;

    // Per-(y,z)-combo hash keys. Combo order c: 0=(y0,z0) 1=(y0,z1) 2=(y1,z0) 3=(y1,z1)
    uint32_t K[4];
    K[0] = ay0 ^ az0 ^ lv;
    K[1] = ay0 ^ az1 ^ lv;
    K[2] = ay1 ^ az0 ^ lv;
    K[3] = ay1 ^ az1 ^ lv;

    const float2* __restrict__ tbl  = (const float2*)tables + (size_t)l * TABLE_SIZE;
    const float4* __restrict__ tbl4 = (const float4*)tbl;

    uint32_t ix1 = ix + 1u;
    bool odd = (ix & 1u) != 0u;

    uint32_t i0[4];
#pragma unroll
    for (int c = 0; c < 4; c++) i0[c] = (ix ^ K[c]) & TABLE_MASK;

    // 4 paired loads: float4 at the aligned pair containing idx0.
    float4 q[4];
#pragma unroll
    for (int c = 0; c < 4; c++) q[c] = __ldg(&tbl4[i0[c] >> 1]);

    // Odd-ix lanes: (ix+1) corner is not adjacent -> 4 extra predicated 8B gathers.
    float2 eo[4];
#pragma unroll
    for (int c = 0; c < 4; c++) eo[c] = make_float2(0.0f, 0.0f);
    if (odd) {
#pragma unroll
        for (int c = 0; c < 4; c++) {
            uint32_t i4 = (ix1 ^ K[c]) & TABLE_MASK;
            eo[c] = __ldg(&tbl[i4]);
        }
    }

    float gx = 1.0f - fx, gy = 1.0f - fy, gz = 1.0f - fz;
    float wyz[4];
    wyz[0] = gy * gz;
    wyz[1] = gy * fz;
    wyz[2] = fy * gz;
    wyz[3] = fy * fz;

    float o0 = 0.0f, o1 = 0.0f;
#pragma unroll
    for (int c = 0; c < 4; c++) {
        bool sel = (i0[c] & 1u) != 0u;           // idx0 in upper half of the pair?
        float e0x = sel ? q[c].z : q[c].x;
        float e0y = sel ? q[c].w : q[c].y;
        // even ix: partner (ix+1 corner) is the other half of the same pair
        float epx = sel ? q[c].x : q[c].z;
        float epy = sel ? q[c].y : q[c].w;
        float e4x = odd ? eo[c].x : epx;
        float e4y = odd ? eo[c].y : epy;

        // combine x-pair first, then apply yz weight
        float mx0 = e0x * gx + e4x * fx;
        float mx1 = e0y * gx + e4y * fx;
        o0 += mx0 * wyz[c];
        o1 += mx1 * wyz[c];
    }

    // out[p, l*2 + {0,1}]; consecutive threads -> contiguous 8B stores.
    float2* orow = (float2*)(out + (size_t)p * (NUM_LEVELS * 2));
    orow[l] = make_float2(o0, o1);
}

extern "C" void kernel_launch(void* const* d_in, const int* in_sizes, int n_in,
                              void* d_out, int out_size) {
    const float* x      = (const float*)d_in[0];
    const float* tables = (const float*)d_in[1];
    float* out          = (float*)d_out;
    int N = in_sizes[0] / 3;

    int total = N * NUM_LEVELS;
    int threads = 256;
    int blocks = (total + threads - 1) / threads;
    hashenc_kernel<<<blocks, threads>>>(x, tables, out, N);
}